// round 10
// baseline (speedup 1.0000x reference)
#include <cuda_runtime.h>
#include <math.h>
#include <math_constants.h>

// Router: logits = x[8192,4096] @ W[4096,64]; per-token top-8 (desc, ties->lower idx);
// softmax over the 8 selected logits.
//
// Accumulation-order emulation of the reference (XLA:CPU -> EigenMatMulF32, gebp):
// k-panels of kc=320 (Eigen's 320 cap), ascending, with a 256 remainder panel;
// within a panel a plain fp32 FMA chain (ascending k); panel sums folded
// sequentially with exact fp32 adds.
//
// Output layout: d_out[0 .. T*8)     = normalized weights (float)
//                d_out[T*8 .. 2*T*8) = selected expert indices (as float)

#define T_TOK 8192
#define D_DIM 4096
#define E_EXP 64
#define TM    32     // tokens per block
#define KC    32     // k-tile in shared
#define KBLK  320    // Eigen gebp k-panel (kc cap)
#define TOPK  8

__device__ __forceinline__ void ffma2(unsigned long long& acc,
                                      unsigned long long a,
                                      unsigned long long b) {
    asm volatile("fma.rn.f32x2 %0, %1, %2, %0;" : "+l"(acc) : "l"(a), "l"(b));
}
__device__ __forceinline__ unsigned long long pack2(float lo, float hi) {
    unsigned long long r;
    asm("mov.b64 %0, {%1, %2};" : "=l"(r) : "f"(lo), "f"(hi));
    return r;
}
__device__ __forceinline__ void unpack2(unsigned long long v, float& lo, float& hi) {
    asm("mov.b64 {%0, %1}, %2;" : "=f"(lo), "=f"(hi) : "l"(v));
}
__device__ __forceinline__ float fadd_rn(float a, float b) {
    float r; asm("add.rn.f32 %0, %1, %2;" : "=f"(r) : "f"(a), "f"(b)); return r;
}
__device__ __forceinline__ float fdiv_rn(float a, float b) {
    float r; asm("div.rn.f32 %0, %1, %2;" : "=f"(r) : "f"(a), "f"(b)); return r;
}

__global__ __launch_bounds__(256, 2) void router_kernel(
    const float* __restrict__ x,     // [T, D]
    const float* __restrict__ w,     // [D, E]
    float* __restrict__ out)         // [2*T*8]
{
    __shared__ float xs[KC][TM];
    __shared__ float ws[KC][E_EXP];
    __shared__ float lg[TM][E_EXP];

    const int tx  = threadIdx.x;              // 0..31 : expert pair 2*tx, 2*tx+1
    const int ty  = threadIdx.y;              // 0..7  : tokens ty*4 .. ty*4+3
    const int tid = ty * 32 + tx;
    const int tok0 = blockIdx.x * TM;

    // running totals (combined panel sums), 4 tokens x 2 experts
    float s0a = 0.f, s0b = 0.f, s1a = 0.f, s1b = 0.f;
    float s2a = 0.f, s2b = 0.f, s3a = 0.f, s3b = 0.f;

    const int xrow = tid >> 3;
    const int xk   = (tid & 7) << 2;

#pragma unroll 1
    for (int kbeg = 0; kbeg < D_DIM; kbeg += KBLK) {
        const int klen = (D_DIM - kbeg < KBLK) ? (D_DIM - kbeg) : KBLK;  // 320 or 256
        // fresh panel accumulators; bit pattern 0 == (0.f, 0.f)
        unsigned long long acc0 = 0ull, acc1 = 0ull, acc2 = 0ull, acc3 = 0ull;

#pragma unroll 1
        for (int kt = 0; kt < klen / KC; kt++) {
            const int k0 = kbeg + kt * KC;
            {
                float4 v = *reinterpret_cast<const float4*>(
                    &x[(size_t)(tok0 + xrow) * D_DIM + k0 + xk]);
                xs[xk + 0][xrow] = v.x;
                xs[xk + 1][xrow] = v.y;
                xs[xk + 2][xrow] = v.z;
                xs[xk + 3][xrow] = v.w;
            }
            {
#pragma unroll
                for (int r = 0; r < 2; r++) {
                    int idx = tid + 256 * r;
                    int row = idx >> 4;
                    int cg  = (idx & 15) << 2;
                    *reinterpret_cast<float4*>(&ws[row][cg]) =
                        *reinterpret_cast<const float4*>(&w[(size_t)(k0 + row) * E_EXP + cg]);
                }
            }
            __syncthreads();

#pragma unroll
            for (int k = 0; k < KC; k++) {
                float2 wv = *reinterpret_cast<const float2*>(&ws[k][tx * 2]);
                unsigned long long w2 = pack2(wv.x, wv.y);
                float4 xv = *reinterpret_cast<const float4*>(&xs[k][ty * 4]);
                ffma2(acc0, pack2(xv.x, xv.x), w2);
                ffma2(acc1, pack2(xv.y, xv.y), w2);
                ffma2(acc2, pack2(xv.z, xv.z), w2);
                ffma2(acc3, pack2(xv.w, xv.w), w2);
            }
            __syncthreads();
        }

        // fold panel sums into totals, sequential in panel order (exact fp32 adds)
        {
            float a, b;
            unpack2(acc0, a, b); s0a = fadd_rn(s0a, a); s0b = fadd_rn(s0b, b);
            unpack2(acc1, a, b); s1a = fadd_rn(s1a, a); s1b = fadd_rn(s1b, b);
            unpack2(acc2, a, b); s2a = fadd_rn(s2a, a); s2b = fadd_rn(s2b, b);
            unpack2(acc3, a, b); s3a = fadd_rn(s3a, a); s3b = fadd_rn(s3b, b);
        }
    }

    // ---- write logits to shared ----
    lg[ty * 4 + 0][tx * 2] = s0a; lg[ty * 4 + 0][tx * 2 + 1] = s0b;
    lg[ty * 4 + 1][tx * 2] = s1a; lg[ty * 4 + 1][tx * 2 + 1] = s1b;
    lg[ty * 4 + 2][tx * 2] = s2a; lg[ty * 4 + 2][tx * 2 + 1] = s2b;
    lg[ty * 4 + 3][tx * 2] = s3a; lg[ty * 4 + 3][tx * 2 + 1] = s3b;
    __syncthreads();

    // ---- per-token top-8 + softmax: warp ty handles tokens ty*4 .. ty*4+3 ----
#pragma unroll
    for (int j = 0; j < 4; j++) {
        const int tok = ty * 4 + j;
        float va = lg[tok][tx];
        float vb = lg[tok][tx + 32];
        const int ea = tx, eb = tx + 32;

        float topv[TOPK];
        int   topi[TOPK];
#pragma unroll
        for (int s = 0; s < TOPK; s++) {
            float v; int e;
            // local best of the two candidates (tie -> lower index; ea < eb always)
            if (va >= vb) { v = va; e = ea; } else { v = vb; e = eb; }
#pragma unroll
            for (int off = 16; off > 0; off >>= 1) {
                float v2 = __shfl_xor_sync(0xffffffffu, v, off);
                int   e2 = __shfl_xor_sync(0xffffffffu, e, off);
                if (v2 > v || (v2 == v && e2 < e)) { v = v2; e = e2; }
            }
            topv[s] = v;
            topi[s] = e;
            if (ea == e) va = -CUDART_INF_F;
            if (eb == e) vb = -CUDART_INF_F;
        }

        if (tx == 0) {
            const float m = topv[0];
            float ev[TOPK];
            float ssum = 0.f;
#pragma unroll
            for (int q = 0; q < TOPK; q++) { ev[q] = expf(topv[q] - m); ssum = fadd_rn(ssum, ev[q]); }
            const size_t base = (size_t)(tok0 + tok) * TOPK;
#pragma unroll
            for (int q = 0; q < TOPK; q++) {
                out[base + q] = fdiv_rn(ev[q], ssum);   // true IEEE division, like exp/sum
                out[(size_t)T_TOK * TOPK + base + q] = (float)topi[q];
            }
        }
    }
}

extern "C" void kernel_launch(void* const* d_in, const int* in_sizes, int n_in,
                              void* d_out, int out_size) {
    const float* x = (const float*)d_in[0];   // [8192, 4096]
    const float* w = (const float*)d_in[1];   // [4096, 64]
    float* out = (float*)d_out;

    dim3 block(32, 8);
    dim3 grid(T_TOK / TM);
    router_kernel<<<grid, block>>>(x, w, out);
}

// round 11
// speedup vs baseline: 1.7374x; 1.7374x over previous
#include <cuda_runtime.h>
#include <math.h>
#include <math_constants.h>

// Router: logits = x[8192,4096] @ W[4096,64]; per-token top-8 (desc, ties->lower idx);
// softmax over the 8 selected logits.
//
// FROZEN ARITHMETIC (bit-identical to the passing R10 kernel):
//   per logit: 13 k-panels (12x320 + 256), ascending; within a panel one plain
//   fp32 FMA chain over ascending k; panel sums folded sequentially with add.rn;
//   topk tie->lower-index; softmax = expf(v - top0), fadd_rn chain, fdiv_rn.
//
// This round changes ONLY the schedule: 8 tok x 8 exp register tile (f32x2 pairs
// over adjacent tokens, pre-duplicated w broadcast from smem), split-K across the
// 13 panels into a __device__ scratch, and a fold+topk kernel.
//
// Output layout: d_out[0 .. T*8)     = normalized weights (float)
//                d_out[T*8 .. 2*T*8) = selected expert indices (as float)

#define T_TOK 8192
#define D_DIM 4096
#define E_EXP 64
#define TOPK  8
#define KBLK  320                 // Eigen-style k-panel
#define NPAN  13                  // 12*320 + 256 = 4096
#define TBLK  256                 // tokens per GEMM CTA
#define NTB   (T_TOK / TBLK)      // 32
#define KC    16                  // k-tile in shared

// panel partial sums: [panel][tokblock][expert][token-in-block]
__device__ float g_part[NPAN][NTB][E_EXP][TBLK];

__device__ __forceinline__ void ffma2(unsigned long long& acc,
                                      unsigned long long a,
                                      unsigned long long b) {
    asm volatile("fma.rn.f32x2 %0, %1, %2, %0;" : "+l"(acc) : "l"(a), "l"(b));
}
__device__ __forceinline__ float fadd_rn(float a, float b) {
    float r; asm("add.rn.f32 %0, %1, %2;" : "=f"(r) : "f"(a), "f"(b)); return r;
}
__device__ __forceinline__ float fdiv_rn(float a, float b) {
    float r; asm("div.rn.f32 %0, %1, %2;" : "=f"(r) : "f"(a), "f"(b)); return r;
}

__global__ __launch_bounds__(256, 2) void gemm_panel_kernel(
    const float* __restrict__ x,     // [T, D]
    const float* __restrict__ w)     // [D, E]
{
    __shared__ float xs[KC][258];    // [k][token] transposed, padded (stride 258 -> conflict-free STS/LDS)
    __shared__ float wsd[KC][132];   // [k][2*expert] duplicated, padded (16B-aligned rows)

    const int tid  = threadIdx.x;
    const int wid  = tid >> 5;       // warp = expert group: experts 8*wid .. 8*wid+7
    const int lane = tid & 31;       // lane -> token pairs {64j+2*lane, +1}, j=0..3
    const int tok0 = blockIdx.x * TBLK;
    const int p    = blockIdx.y;     // panel index
    const int kbeg = p * KBLK;
    const int ntile = (p == NPAN - 1) ? (D_DIM - (NPAN - 1) * KBLK) / KC : KBLK / KC;

    unsigned long long acc[4][8];    // [token-pair j][expert e] = {logit[t], logit[t+1]}
#pragma unroll
    for (int j = 0; j < 4; j++)
#pragma unroll
        for (int e = 0; e < 8; e++) acc[j][e] = 0ull;

#pragma unroll 1
    for (int t = 0; t < ntile; t++) {
        const int k0 = kbeg + t * KC;

        // x tile: 256 tokens x 16 k, transposed into xs[k][tok]
#pragma unroll
        for (int r = 0; r < 4; r++) {
            int idx = tid + 256 * r;         // 0..1023
            int tok = idx >> 2;              // 0..255
            int kq  = idx & 3;               // float4 index within the 16-k row
            float4 v = *reinterpret_cast<const float4*>(
                &x[(size_t)(tok0 + tok) * D_DIM + k0 + 4 * kq]);
            xs[4 * kq + 0][tok] = v.x;
            xs[4 * kq + 1][tok] = v.y;
            xs[4 * kq + 2][tok] = v.z;
            xs[4 * kq + 3][tok] = v.w;
        }
        // w tile: 16 k x 64 experts, stored duplicated: wsd[k][2e] = wsd[k][2e+1] = w[k][e]
        {
            int r = tid >> 4;                // 0..15
            int m = tid & 15;                // expert quad
            float4 v = *reinterpret_cast<const float4*>(
                &w[(size_t)(k0 + r) * E_EXP + 4 * m]);
            wsd[r][8 * m + 0] = v.x; wsd[r][8 * m + 1] = v.x;
            wsd[r][8 * m + 2] = v.y; wsd[r][8 * m + 3] = v.y;
            wsd[r][8 * m + 4] = v.z; wsd[r][8 * m + 5] = v.z;
            wsd[r][8 * m + 6] = v.w; wsd[r][8 * m + 7] = v.w;
        }
        __syncthreads();

#pragma unroll
        for (int kk = 0; kk < KC; kk++) {
            // 8 duplicated-expert pairs for this warp's experts (broadcast reads)
            ulonglong2 q0 = *reinterpret_cast<const ulonglong2*>(&wsd[kk][16 * wid + 0]);
            ulonglong2 q1 = *reinterpret_cast<const ulonglong2*>(&wsd[kk][16 * wid + 4]);
            ulonglong2 q2 = *reinterpret_cast<const ulonglong2*>(&wsd[kk][16 * wid + 8]);
            ulonglong2 q3 = *reinterpret_cast<const ulonglong2*>(&wsd[kk][16 * wid + 12]);
            unsigned long long w2[8] = {q0.x, q0.y, q1.x, q1.y, q2.x, q2.y, q3.x, q3.y};

            // 4 adjacent-token pairs for this lane (coalesced conflict-free LDS.64)
            unsigned long long xp[4];
#pragma unroll
            for (int j = 0; j < 4; j++)
                xp[j] = *reinterpret_cast<const unsigned long long*>(
                    &xs[kk][64 * j + 2 * lane]);

#pragma unroll
            for (int j = 0; j < 4; j++)
#pragma unroll
                for (int e = 0; e < 8; e++)
                    ffma2(acc[j][e], xp[j], w2[e]);
        }
        __syncthreads();
    }

    // store panel partials: adjacent tokens -> STG.64, fully coalesced per (j,e)
#pragma unroll
    for (int j = 0; j < 4; j++)
#pragma unroll
        for (int e = 0; e < 8; e++)
            *reinterpret_cast<unsigned long long*>(
                &g_part[p][blockIdx.x][8 * wid + e][64 * j + 2 * lane]) = acc[j][e];
}

__global__ __launch_bounds__(256) void fold_topk_kernel(float* __restrict__ out)
{
    const int tb = blockIdx.x;       // token block 0..31
    const int t  = threadIdx.x;      // token within block 0..255
    const int gtok = tb * TBLK + t;

    // fold the 13 panel partials sequentially (exact adds, ascending panel order)
    float lg[E_EXP];
#pragma unroll
    for (int e = 0; e < E_EXP; e++) {
        float s = 0.f;
#pragma unroll
        for (int p = 0; p < NPAN; p++)
            s = fadd_rn(s, g_part[p][tb][e][t]);   // (0+p0)=p0, then ((p0+p1)+p2)...
        lg[e] = s;
    }

    // top-8, descending, tie -> lower index (strict > on ascending scan)
    float topv[TOPK]; int topi[TOPK];
#pragma unroll
    for (int s = 0; s < TOPK; s++) {
        float best = -CUDART_INF_F; int bi = 0;
#pragma unroll
        for (int e = 0; e < E_EXP; e++)
            if (lg[e] > best) { best = lg[e]; bi = e; }
        topv[s] = best; topi[s] = bi;
#pragma unroll
        for (int e = 0; e < E_EXP; e++)
            lg[e] = (e == bi) ? -CUDART_INF_F : lg[e];
    }

    // softmax over the 8 selected logits (identical expression order to R10)
    const float m = topv[0];
    float ev[TOPK]; float ssum = 0.f;
#pragma unroll
    for (int q = 0; q < TOPK; q++) { ev[q] = expf(topv[q] - m); ssum = fadd_rn(ssum, ev[q]); }

    const size_t base = (size_t)gtok * TOPK;
#pragma unroll
    for (int q = 0; q < TOPK; q++) {
        out[base + q] = fdiv_rn(ev[q], ssum);
        out[(size_t)T_TOK * TOPK + base + q] = (float)topi[q];
    }
}

extern "C" void kernel_launch(void* const* d_in, const int* in_sizes, int n_in,
                              void* d_out, int out_size) {
    const float* x = (const float*)d_in[0];   // [8192, 4096]
    const float* w = (const float*)d_in[1];   // [4096, 64]
    float* out = (float*)d_out;

    gemm_panel_kernel<<<dim3(NTB, NPAN), 256>>>(x, w);
    fold_topk_kernel<<<NTB, 256>>>(out);
}

// round 12
// speedup vs baseline: 1.7969x; 1.0343x over previous
#include <cuda_runtime.h>
#include <math.h>
#include <math_constants.h>

// Router: logits = x[8192,4096] @ W[4096,64]; per-token top-8 (desc, ties->lower idx);
// softmax over the 8 selected logits.
//
// FROZEN ARITHMETIC (bit-identical to passing R10/R11 kernels):
//   per logit: 13 k-panels (12x320 + 256), ascending; within a panel one plain
//   fp32 FMA chain over ascending k; panel sums folded sequentially with add.rn;
//   topk desc tie->lower-index; softmax = expf(v - top0), fadd_rn chain, fdiv_rn.
//
// R12 schedule changes only: double-buffered GEMM smem pipeline; fold kernel
// re-gridded to 256 CTAs with warp-parallel fold + warp-shuffle topk.
//
// Output layout: d_out[0 .. T*8)     = normalized weights (float)
//                d_out[T*8 .. 2*T*8) = selected expert indices (as float)

#define T_TOK 8192
#define D_DIM 4096
#define E_EXP 64
#define TOPK  8
#define KBLK  320                 // Eigen-style k-panel
#define NPAN  13                  // 12*320 + 256 = 4096
#define TBLK  256                 // tokens per GEMM CTA
#define NTB   (T_TOK / TBLK)      // 32
#define KC    16                  // k-tile in shared

// panel partial sums: [panel][tokblock][expert][token-in-block]
__device__ float g_part[NPAN][NTB][E_EXP][TBLK];

__device__ __forceinline__ void ffma2(unsigned long long& acc,
                                      unsigned long long a,
                                      unsigned long long b) {
    asm volatile("fma.rn.f32x2 %0, %1, %2, %0;" : "+l"(acc) : "l"(a), "l"(b));
}
__device__ __forceinline__ float fadd_rn(float a, float b) {
    float r; asm("add.rn.f32 %0, %1, %2;" : "=f"(r) : "f"(a), "f"(b)); return r;
}
__device__ __forceinline__ float fdiv_rn(float a, float b) {
    float r; asm("div.rn.f32 %0, %1, %2;" : "=f"(r) : "f"(a), "f"(b)); return r;
}

__global__ __launch_bounds__(256, 2) void gemm_panel_kernel(
    const float* __restrict__ x,     // [T, D]
    const float* __restrict__ w)     // [D, E]
{
    __shared__ float xs[2][KC][258];   // [buf][k][token], padded
    __shared__ float wsd[2][KC][132];  // [buf][k][2*expert] duplicated, padded

    const int tid  = threadIdx.x;
    const int wid  = tid >> 5;       // warp = expert group: experts 8*wid .. 8*wid+7
    const int lane = tid & 31;       // lane -> token pairs {64j+2*lane, +1}, j=0..3
    const int tok0 = blockIdx.x * TBLK;
    const int p    = blockIdx.y;     // panel index
    const int kbeg = p * KBLK;
    const int ntile = (p == NPAN - 1) ? (D_DIM - (NPAN - 1) * KBLK) / KC : KBLK / KC;

    // addressing for the x tile load: 4 float4 per thread
    const int ltok = tid >> 2;             // 0..63 base token (x4 via r)
    const int lkq  = tid & 3;              // float4 index within the 16-k row

    unsigned long long acc[4][8];
#pragma unroll
    for (int j = 0; j < 4; j++)
#pragma unroll
        for (int e = 0; e < 8; e++) acc[j][e] = 0ull;

    float4 xv[4];
    float4 wv;

    // ---- preload tile 0 ----
    {
        const int k0 = kbeg;
#pragma unroll
        for (int r = 0; r < 4; r++)
            xv[r] = *reinterpret_cast<const float4*>(
                &x[(size_t)(tok0 + ltok + 64 * r) * D_DIM + k0 + 4 * lkq]);
        wv = *reinterpret_cast<const float4*>(
            &w[(size_t)(k0 + (tid >> 4)) * E_EXP + 4 * (tid & 15)]);
    }
    {
#pragma unroll
        for (int r = 0; r < 4; r++) {
            int tok = ltok + 64 * r;
            xs[0][4 * lkq + 0][tok] = xv[r].x;
            xs[0][4 * lkq + 1][tok] = xv[r].y;
            xs[0][4 * lkq + 2][tok] = xv[r].z;
            xs[0][4 * lkq + 3][tok] = xv[r].w;
        }
        int r = tid >> 4, m = tid & 15;
        wsd[0][r][8 * m + 0] = wv.x; wsd[0][r][8 * m + 1] = wv.x;
        wsd[0][r][8 * m + 2] = wv.y; wsd[0][r][8 * m + 3] = wv.y;
        wsd[0][r][8 * m + 4] = wv.z; wsd[0][r][8 * m + 5] = wv.z;
        wsd[0][r][8 * m + 6] = wv.w; wsd[0][r][8 * m + 7] = wv.w;
    }
    __syncthreads();

#pragma unroll 1
    for (int t = 0; t < ntile; t++) {
        const int cur = t & 1;
        const bool more = (t + 1) < ntile;

        // prefetch tile t+1 into registers (latency overlapped with compute below)
        if (more) {
            const int k0 = kbeg + (t + 1) * KC;
#pragma unroll
            for (int r = 0; r < 4; r++)
                xv[r] = *reinterpret_cast<const float4*>(
                    &x[(size_t)(tok0 + ltok + 64 * r) * D_DIM + k0 + 4 * lkq]);
            wv = *reinterpret_cast<const float4*>(
                &w[(size_t)(k0 + (tid >> 4)) * E_EXP + 4 * (tid & 15)]);
        }

        // compute on current buffer
#pragma unroll
        for (int kk = 0; kk < KC; kk++) {
            ulonglong2 q0 = *reinterpret_cast<const ulonglong2*>(&wsd[cur][kk][16 * wid + 0]);
            ulonglong2 q1 = *reinterpret_cast<const ulonglong2*>(&wsd[cur][kk][16 * wid + 4]);
            ulonglong2 q2 = *reinterpret_cast<const ulonglong2*>(&wsd[cur][kk][16 * wid + 8]);
            ulonglong2 q3 = *reinterpret_cast<const ulonglong2*>(&wsd[cur][kk][16 * wid + 12]);
            unsigned long long w2[8] = {q0.x, q0.y, q1.x, q1.y, q2.x, q2.y, q3.x, q3.y};

            unsigned long long xp[4];
#pragma unroll
            for (int j = 0; j < 4; j++)
                xp[j] = *reinterpret_cast<const unsigned long long*>(
                    &xs[cur][kk][64 * j + 2 * lane]);

#pragma unroll
            for (int j = 0; j < 4; j++)
#pragma unroll
                for (int e = 0; e < 8; e++)
                    ffma2(acc[j][e], xp[j], w2[e]);
        }

        // stage tile t+1 into the other buffer
        if (more) {
            const int nxt = cur ^ 1;
#pragma unroll
            for (int r = 0; r < 4; r++) {
                int tok = ltok + 64 * r;
                xs[nxt][4 * lkq + 0][tok] = xv[r].x;
                xs[nxt][4 * lkq + 1][tok] = xv[r].y;
                xs[nxt][4 * lkq + 2][tok] = xv[r].z;
                xs[nxt][4 * lkq + 3][tok] = xv[r].w;
            }
            int r = tid >> 4, m = tid & 15;
            wsd[nxt][r][8 * m + 0] = wv.x; wsd[nxt][r][8 * m + 1] = wv.x;
            wsd[nxt][r][8 * m + 2] = wv.y; wsd[nxt][r][8 * m + 3] = wv.y;
            wsd[nxt][r][8 * m + 4] = wv.z; wsd[nxt][r][8 * m + 5] = wv.z;
            wsd[nxt][r][8 * m + 6] = wv.w; wsd[nxt][r][8 * m + 7] = wv.w;
        }
        __syncthreads();
    }

    // store panel partials (coalesced STG.64 per (j,e))
#pragma unroll
    for (int j = 0; j < 4; j++)
#pragma unroll
        for (int e = 0; e < 8; e++)
            *reinterpret_cast<unsigned long long*>(
                &g_part[p][blockIdx.x][8 * wid + e][64 * j + 2 * lane]) = acc[j][e];
}

// ---- fold + topk: 256 CTAs x 8 warps; 32 tokens per CTA ----
__global__ __launch_bounds__(256) void fold_topk_kernel(float* __restrict__ out)
{
    __shared__ float lgs[32][65];    // [token-in-cta][expert], padded

    const int tid  = threadIdx.x;
    const int wid  = tid >> 5;       // expert group for the fold phase
    const int lane = tid & 31;       // token-in-cta for the fold phase
    const int tb   = blockIdx.x >> 3;          // token block (g_part dim)
    const int t0   = (blockIdx.x & 7) * 32;    // token offset within block

    // fold: warp wid folds experts 8*wid..8*wid+7 for token t0+lane
#pragma unroll
    for (int e8 = 0; e8 < 8; e8++) {
        const int e = 8 * wid + e8;
        float s = 0.f;
#pragma unroll
        for (int p = 0; p < NPAN; p++)
            s = fadd_rn(s, g_part[p][tb][e][t0 + lane]);
        lgs[lane][e] = s;
    }
    __syncthreads();

    // topk + softmax: warp wid handles tokens t0 + 4*wid .. t0 + 4*wid + 3
#pragma unroll 1
    for (int j = 0; j < 4; j++) {
        const int tl = 4 * wid + j;           // token-in-cta
        float va = lgs[tl][lane];
        float vb = lgs[tl][lane + 32];
        const int ea = lane, eb = lane + 32;

        float topv[TOPK];
        int   topi[TOPK];
#pragma unroll
        for (int s = 0; s < TOPK; s++) {
            float v; int e;
            if (va >= vb) { v = va; e = ea; } else { v = vb; e = eb; }
#pragma unroll
            for (int off = 16; off > 0; off >>= 1) {
                float v2 = __shfl_xor_sync(0xffffffffu, v, off);
                int   e2 = __shfl_xor_sync(0xffffffffu, e, off);
                if (v2 > v || (v2 == v && e2 < e)) { v = v2; e = e2; }
            }
            topv[s] = v;
            topi[s] = e;
            if (ea == e) va = -CUDART_INF_F;
            if (eb == e) vb = -CUDART_INF_F;
        }

        if (lane == 0) {
            const float m = topv[0];
            float ev[TOPK];
            float ssum = 0.f;
#pragma unroll
            for (int q = 0; q < TOPK; q++) { ev[q] = expf(topv[q] - m); ssum = fadd_rn(ssum, ev[q]); }
            const int gtok = tb * TBLK + t0 + tl;
            const size_t base = (size_t)gtok * TOPK;
#pragma unroll
            for (int q = 0; q < TOPK; q++) {
                out[base + q] = fdiv_rn(ev[q], ssum);
                out[(size_t)T_TOK * TOPK + base + q] = (float)topi[q];
            }
        }
    }
}

extern "C" void kernel_launch(void* const* d_in, const int* in_sizes, int n_in,
                              void* d_out, int out_size) {
    const float* x = (const float*)d_in[0];   // [8192, 4096]
    const float* w = (const float*)d_in[1];   // [4096, 64]
    float* out = (float*)d_out;

    gemm_panel_kernel<<<dim3(NTB, NPAN), 256>>>(x, w);
    fold_topk_kernel<<<T_TOK / 32, 256>>>(out);
}